// round 11
// baseline (speedup 1.0000x reference)
#include <cuda_runtime.h>
#include <cuda_fp16.h>
#include <cstdint>

// Fixed shapes
#define B 2
#define D 160
#define H 160
#define W 160
#define NVOX (B * D * H * W)          // 8,192,000
#define HW (H * W)                    // 25,600

#define HSEGS 4
#define HSEG_LEN (H / HSEGS)          // 40
#define KA_GRID (D * HSEGS)           // 640 blocks per batch
#define KA_THREADS 80                 // one float2 (2 outputs) per thread
#define SROW 172                      // 6 pad + 160 + 6 pad

#define KB_SEGS 10
#define KB_SEGLEN (D / KB_SEGS)       // 16
#define KB_HBLK 2
#define KB_THREADS 80                 // 40 half4-lanes x 2 h-rows
#define KB_GRID ((H / KB_HBLK) * KB_SEGS)   // 800 blocks per batch

// SSIM constants (faithful: C1 = K1 / data_range^2)
#define C1F 5.9604644775390625e-10f   // 0.01 / 4096^2
#define C2F 1.7881393432617188e-09f   // 0.03 / 4096^2
#define INV_WIN3 (1.0f / 1331.0f)

// Intermediate: 5 quantity planes, fp16 packed as half2 (w-pairs).
__device__ __half2 g_bufB[5 * (NVOX / 2)];
__device__ float g_l1part[B * KA_GRID];
__device__ float g_ssimpart[B * KB_GRID];

__device__ __forceinline__ void cp_async8(uint32_t saddr, const void* g) {
    asm volatile("cp.async.ca.shared.global [%0], [%1], 8;" :: "r"(saddr), "l"(g));
}
__device__ __forceinline__ void cp_commit() {
    asm volatile("cp.async.commit_group;");
}
__device__ __forceinline__ void cp_wait2() {
    asm volatile("cp.async.wait_group 2;");
}

// ---------------------------------------------------------------------------
// Kernel A: fused W+H box sums (x, y, x^2, y^2, xy), 2 outputs per thread.
// 11-slot cp.async staging pipeline (depth 3), float2 taps, incremental
// second output, register ring. Output stored as half2. One batch per launch.
// grid = D*HSEGS = 640, 80 threads, min-blocks 4 (regfile ceiling, R9 lesson).
// ---------------------------------------------------------------------------
#define KA_FETCH(ROW, SLOT) { \
    const int _r = (ROW); \
    if (_r >= 0 && _r < H) { \
        cp_async8(sx_base + (SLOT) * (SROW * 4) + (6 + w) * 4, x + pb + _r * W + w); \
        cp_async8(sy_base + (SLOT) * (SROW * 4) + (6 + w) * 4, y + pb + _r * W + w); \
    } else { \
        *(float2*)&sx[SLOT][6 + w] = make_float2(0.f, 0.f); \
        *(float2*)&sy[SLOT][6 + w] = make_float2(0.f, 0.f); \
    } \
    cp_commit(); }

#define KA_STEP(TT) { \
    cp_wait2(); \
    __syncthreads(); \
    { \
        const float2* rx2 = (const float2*)&sx[TT][w]; \
        const float2* ry2 = (const float2*)&sy[TT][w]; \
        float xv[14], yv[14]; \
        _Pragma("unroll") \
        for (int i = 0; i < 7; i++) { \
            float2 t2 = rx2[i]; xv[2*i] = t2.x; xv[2*i+1] = t2.y; \
            float2 u2 = ry2[i]; yv[2*i] = u2.x; yv[2*i+1] = u2.y; \
        } \
        float ax = xv[1], ay = yv[1]; \
        float axx = xv[1]*xv[1], ayy = yv[1]*yv[1], axy = xv[1]*yv[1]; \
        _Pragma("unroll") \
        for (int i = 2; i <= 11; i++) { \
            ax += xv[i]; ay += yv[i]; \
            axx = fmaf(xv[i], xv[i], axx); \
            ayy = fmaf(yv[i], yv[i], ayy); \
            axy = fmaf(xv[i], yv[i], axy); \
        } \
        float dax = xv[12] - xv[1], day = yv[12] - yv[1]; \
        float ax1 = ax + dax, ay1 = ay + day; \
        float axx1 = fmaf(dax, xv[12] + xv[1], axx); \
        float ayy1 = fmaf(day, yv[12] + yv[1], ayy); \
        float axy1 = fmaf(-xv[1], yv[1], fmaf(xv[12], yv[12], axy)); \
        rg0[TT] = make_float2(ax, ax1);   s0.x += ax;  s0.y += ax1; \
        rg1[TT] = make_float2(ay, ay1);   s1.x += ay;  s1.y += ay1; \
        rg2[TT] = make_float2(axx, axx1); s2.x += axx; s2.y += axx1; \
        rg3[TT] = make_float2(ayy, ayy1); s3.x += ayy; s3.y += ayy1; \
        rg4[TT] = make_float2(axy, axy1); s4.x += axy; s4.y += axy1; \
        if (r >= h0 && r < h1) { \
            float e0 = fabsf(xv[6] - yv[6]); \
            l1acc += (e0 < 1.f) ? 0.5f * e0 * e0 : e0 - 0.5f; \
            float e1 = fabsf(xv[7] - yv[7]); \
            l1acc += (e1 < 1.f) ? 0.5f * e1 * e1 : e1 - 0.5f; \
        } \
    } \
    KA_FETCH(r + 3, (TT + 3) % 11) \
    if (t >= 10) { \
        const int hh = h0 + t - 10; \
        const int o2 = (pb + hh * W + w) >> 1; \
        g_bufB[0 * (NVOX/2) + o2] = __float22half2_rn(s0); \
        g_bufB[1 * (NVOX/2) + o2] = __float22half2_rn(s1); \
        g_bufB[2 * (NVOX/2) + o2] = __float22half2_rn(s2); \
        g_bufB[3 * (NVOX/2) + o2] = __float22half2_rn(s3); \
        g_bufB[4 * (NVOX/2) + o2] = __float22half2_rn(s4); \
        float2 z; \
        z = rg0[(TT + 1) % 11]; s0.x -= z.x; s0.y -= z.y; \
        z = rg1[(TT + 1) % 11]; s1.x -= z.x; s1.y -= z.y; \
        z = rg2[(TT + 1) % 11]; s2.x -= z.x; s2.y -= z.y; \
        z = rg3[(TT + 1) % 11]; s3.x -= z.x; s3.y -= z.y; \
        z = rg4[(TT + 1) % 11]; s4.x -= z.x; s4.y -= z.y; \
    } \
    r++; t++; }

__global__ __launch_bounds__(KA_THREADS, 4) void kA_wh(const float* __restrict__ x,
                                                       const float* __restrict__ y,
                                                       const int bb) {
    __shared__ __align__(16) float sx[11][SROW];
    __shared__ __align__(16) float sy[11][SROW];
    __shared__ float red[KA_THREADS];

    const int bx = blockIdx.x;
    const int seg = bx % HSEGS;
    const int d = bx / HSEGS;          // 0..159
    const int w2 = threadIdx.x;        // 0..79
    const int w = 2 * w2;

    const int h0 = seg * HSEG_LEN;
    const int h1 = h0 + HSEG_LEN;
    const int pb = (bb * D + d) * HW;

    const uint32_t sx_base = (uint32_t)__cvta_generic_to_shared(&sx[0][0]);
    const uint32_t sy_base = (uint32_t)__cvta_generic_to_shared(&sy[0][0]);

    // zero pads once (cp.async never touches indices 0..5 / 166..171)
    if (w2 < 12) {
        int p = (w2 < 6) ? w2 : (160 + w2);
#pragma unroll
        for (int s = 0; s < 11; s++) { sx[s][p] = 0.f; sy[s][p] = 0.f; }
    }

    // prologue: fetch rows h0-5 .. h0-3 into slots 0..2
    KA_FETCH(h0 - 5, 0)
    KA_FETCH(h0 - 4, 1)
    KA_FETCH(h0 - 3, 2)

    float2 s0 = {0.f, 0.f}, s1 = {0.f, 0.f}, s2 = {0.f, 0.f};
    float2 s3 = {0.f, 0.f}, s4 = {0.f, 0.f};
    float l1acc = 0.f;
    float2 rg0[11], rg1[11], rg2[11], rg3[11], rg4[11];
    int r = h0 - 5;
    int t = 0;

#pragma unroll 1
    for (int tc = 0; tc < 4; tc++) {
        KA_STEP(0) KA_STEP(1) KA_STEP(2) KA_STEP(3) KA_STEP(4) KA_STEP(5)
        KA_STEP(6) KA_STEP(7) KA_STEP(8) KA_STEP(9) KA_STEP(10)
    }
    KA_STEP(0) KA_STEP(1) KA_STEP(2) KA_STEP(3) KA_STEP(4) KA_STEP(5)

    // deterministic block reduction of l1acc over 80 threads
    red[w2] = l1acc;
    __syncthreads();
    if (w2 < 40) red[w2] += red[w2 + 40];
    __syncthreads();
    if (w2 < 20) red[w2] += red[w2 + 20];
    __syncthreads();
    if (w2 < 10) red[w2] += red[w2 + 10];
    __syncthreads();
    if (w2 < 5) red[w2] += red[w2 + 5];
    __syncthreads();
    if (w2 == 0) {
        g_l1part[bb * KA_GRID + bx] = red[0] + red[1] + red[2] + red[3] + red[4];
    }
}
#undef KA_STEP
#undef KA_FETCH

// ---------------------------------------------------------------------------
// SSIM scalar helper
// ---------------------------------------------------------------------------
__device__ __forceinline__ float ssim_loss(float s0, float s1, float s2,
                                           float s3, float s4) {
    float mux = s0 * INV_WIN3;
    float muy = s1 * INV_WIN3;
    float mux2 = mux * mux;
    float muy2 = muy * muy;
    float muxy = mux * muy;
    float sxx = s2 * INV_WIN3 - mux2;
    float syy = s3 * INV_WIN3 - muy2;
    float sxy = s4 * INV_WIN3 - muxy;
    float num = (2.f * muxy + C1F) * (2.f * sxy + C2F);
    float den = (mux2 + muy2 + C1F) * (sxx + syy + C2F);
    float ssim = num / (den + 1e-8f);
    float loss = (1.f - ssim) * 0.5f;
    return fminf(fmaxf(loss, 0.f), 1.f);
}

// half4 load (uint2) -> float4
__device__ __forceinline__ float4 ldh4(const __half2* p) {
    uint2 u = *reinterpret_cast<const uint2*>(p);
    __half2 h0 = *reinterpret_cast<__half2*>(&u.x);
    __half2 h1 = *reinterpret_cast<__half2*>(&u.y);
    float2 f0 = __half22float2(h0);
    float2 f1 = __half22float2(h1);
    return make_float4(f0.x, f0.y, f1.x, f1.y);
}

#define ACC4(S, V) { S.x += V.x; S.y += V.y; S.z += V.z; S.w += V.w; }
#define UPD4(S, A, Bv) { S.x += A.x - Bv.x; S.y += A.y - Bv.y; \
                         S.z += A.z - Bv.z; S.w += A.w - Bv.w; }

// ---------------------------------------------------------------------------
// Kernel B: box-sum along D (running sums, leading+trailing edges) + SSIM +
// block reduction. half4 loads, 4 w-outputs per thread, 2 h-rows/block,
// 16-deep d segments. One batch per launch: grid = 800, 80 threads.
// ---------------------------------------------------------------------------
__global__ __launch_bounds__(KB_THREADS) void kB_dpass_ssim(const int bb) {
    __shared__ float red[KB_THREADS];

    const int bid = blockIdx.x;
    const int seg = bid % KB_SEGS;
    const int hq = bid / KB_SEGS;      // 0..79

    const int tid = threadIdx.x;
    const int lane = tid % (W / 4);    // 0..39, 4-wide w chunk
    const int row = tid / (W / 4);     // 0..1
    const int h = hq * KB_HBLK + row;

    const int d0 = seg * KB_SEGLEN;
    const int colh2 = (bb * (D * HW) + h * W) / 2 + lane * 2;  // half2 units
    const int sth2 = HW / 2;

    const __half2* __restrict__ q0 = g_bufB + 0 * (NVOX / 2);
    const __half2* __restrict__ q1 = g_bufB + 1 * (NVOX / 2);
    const __half2* __restrict__ q2 = g_bufB + 2 * (NVOX / 2);
    const __half2* __restrict__ q3 = g_bufB + 3 * (NVOX / 2);
    const __half2* __restrict__ q4 = g_bufB + 4 * (NVOX / 2);

    float4 s0 = {0,0,0,0}, s1 = {0,0,0,0}, s2 = {0,0,0,0};
    float4 s3 = {0,0,0,0}, s4 = {0,0,0,0};
    {
        int lo = d0 - 5; if (lo < 0) lo = 0;
        int hi = d0 + 5; if (hi > D - 1) hi = D - 1;
        for (int d = lo; d <= hi; d++) {
            int id = colh2 + d * sth2;
            float4 v;
            v = ldh4(q0 + id); ACC4(s0, v)
            v = ldh4(q1 + id); ACC4(s1, v)
            v = ldh4(q2 + id); ACC4(s2, v)
            v = ldh4(q3 + id); ACC4(s3, v)
            v = ldh4(q4 + id); ACC4(s4, v)
        }
    }

    float acc = 0.f;
#pragma unroll 4
    for (int i = 0; i < KB_SEGLEN; i++) {
        const int d = d0 + i;
        const int dn = d + 6;
        const int dp = d - 5;

        float4 a0 = {0,0,0,0}, a1 = {0,0,0,0}, a2 = {0,0,0,0};
        float4 a3 = {0,0,0,0}, a4 = {0,0,0,0};
        float4 b0 = {0,0,0,0}, b1 = {0,0,0,0}, b2 = {0,0,0,0};
        float4 b3 = {0,0,0,0}, b4 = {0,0,0,0};
        if (dn < D) {
            int id = colh2 + dn * sth2;
            a0 = ldh4(q0 + id); a1 = ldh4(q1 + id); a2 = ldh4(q2 + id);
            a3 = ldh4(q3 + id); a4 = ldh4(q4 + id);
        }
        if (dp >= 0) {
            int id = colh2 + dp * sth2;
            b0 = ldh4(q0 + id); b1 = ldh4(q1 + id); b2 = ldh4(q2 + id);
            b3 = ldh4(q3 + id); b4 = ldh4(q4 + id);
        }

        acc += ssim_loss(s0.x, s1.x, s2.x, s3.x, s4.x);
        acc += ssim_loss(s0.y, s1.y, s2.y, s3.y, s4.y);
        acc += ssim_loss(s0.z, s1.z, s2.z, s3.z, s4.z);
        acc += ssim_loss(s0.w, s1.w, s2.w, s3.w, s4.w);

        UPD4(s0, a0, b0)
        UPD4(s1, a1, b1)
        UPD4(s2, a2, b2)
        UPD4(s3, a3, b3)
        UPD4(s4, a4, b4)
    }

    // deterministic block reduction over 80 threads
    red[tid] = acc;
    __syncthreads();
    if (tid < 40) red[tid] += red[tid + 40];
    __syncthreads();
    if (tid < 20) red[tid] += red[tid + 20];
    __syncthreads();
    if (tid < 10) red[tid] += red[tid + 10];
    __syncthreads();
    if (tid < 5) red[tid] += red[tid + 5];
    __syncthreads();
    if (tid == 0) {
        g_ssimpart[bb * KB_GRID + bid] = red[0] + red[1] + red[2] + red[3] + red[4];
    }
}

// ---------------------------------------------------------------------------
// Kernel C: final deterministic reduction.
// ---------------------------------------------------------------------------
__global__ __launch_bounds__(256) void kC_final(float* __restrict__ out) {
    __shared__ double sh[256];
    const int t = threadIdx.x;

    double a = 0.0;
    for (int i = t; i < B * KA_GRID; i += 256) a += (double)g_l1part[i];
    double bsum = 0.0;
    for (int i = t; i < B * KB_GRID; i += 256) bsum += (double)g_ssimpart[i];

    sh[t] = a;
    __syncthreads();
#pragma unroll
    for (int s = 128; s > 0; s >>= 1) {
        if (t < s) sh[t] += sh[t + s];
        __syncthreads();
    }
    double l1sum = sh[0];
    __syncthreads();

    sh[t] = bsum;
    __syncthreads();
#pragma unroll
    for (int s = 128; s > 0; s >>= 1) {
        if (t < s) sh[t] += sh[t + s];
        __syncthreads();
    }

    if (t == 0) {
        double ssimsum = sh[0];
        double n = (double)NVOX;
        out[0] = (float)(0.85 * (ssimsum / n) + 0.15 * (l1sum / n));
    }
}

// ---------------------------------------------------------------------------
// Launch: batch-split pipeline across two streams (fork/join via events so
// the graph capture records the parallelism).
//   s0: kA(b0) -> kA(b1) -> kB(b1) -> [wait e_join] -> kC
//   s1: [wait e_fork(after kA b0)] -> kB(b0) -> record e_join
// Streams/events are created once (host resources only; identical launch
// sequence every call).
// ---------------------------------------------------------------------------
extern "C" void kernel_launch(void* const* d_in, const int* in_sizes, int n_in,
                              void* d_out, int out_size) {
    const float* pred = (const float*)d_in[0];
    const float* target = (const float*)d_in[1];
    float* out = (float*)d_out;

    static cudaStream_t s1 = nullptr;
    static cudaEvent_t eFork = nullptr, eJoin = nullptr;
    if (s1 == nullptr) {
        cudaStreamCreateWithFlags(&s1, cudaStreamNonBlocking);
        cudaEventCreateWithFlags(&eFork, cudaEventDisableTiming);
        cudaEventCreateWithFlags(&eJoin, cudaEventDisableTiming);
    }

    // batch 0 first pass
    kA_wh<<<KA_GRID, KA_THREADS>>>(pred, target, 0);
    cudaEventRecord(eFork, 0);

    // batch 1 first pass (default stream) overlaps batch 0 second pass (s1)
    kA_wh<<<KA_GRID, KA_THREADS>>>(pred, target, 1);

    cudaStreamWaitEvent(s1, eFork, 0);
    kB_dpass_ssim<<<KB_GRID, KB_THREADS, 0, s1>>>(0);
    cudaEventRecord(eJoin, s1);

    kB_dpass_ssim<<<KB_GRID, KB_THREADS>>>(1);

    cudaStreamWaitEvent(0, eJoin, 0);
    kC_final<<<1, 256>>>(out);
}

// round 12
// speedup vs baseline: 1.0733x; 1.0733x over previous
#include <cuda_runtime.h>
#include <cuda_fp16.h>
#include <cstdint>

// Fixed shapes
#define B 2
#define D 160
#define H 160
#define W 160
#define NVOX (B * D * H * W)          // 8,192,000
#define HW (H * W)                    // 25,600

#define HSEGS 4
#define HSEG_LEN (H / HSEGS)          // 40
#define A_BLOCKS (B * D * HSEGS)      // 1280
#define KA_THREADS 80                 // one float2 (2 outputs) per thread
#define SROW 172                      // 6 pad + 160 + 6 pad

#define KB_SEGS 10
#define KB_SEGLEN (D / KB_SEGS)       // 16
#define KB_HBLK 2
#define KB_THREADS 80                 // 40 half4-lanes x 2 h-rows
#define KB_BLOCKS (B * (H / KB_HBLK) * KB_SEGS)  // 1600

// SSIM constants (faithful: C1 = K1 / data_range^2)
#define C1F 5.9604644775390625e-10f   // 0.01 / 4096^2
#define C2F 1.7881393432617188e-09f   // 0.03 / 4096^2
#define INV_WIN3 (1.0f / 1331.0f)

// Intermediate: 5 quantity planes, fp16 packed as half2 (w-pairs).
__device__ __half2 g_bufB[5 * (NVOX / 2)];
__device__ float g_l1part[A_BLOCKS];
__device__ float g_ssimpart[KB_BLOCKS];

__device__ __forceinline__ void cp_async8(uint32_t saddr, const void* g) {
    asm volatile("cp.async.ca.shared.global [%0], [%1], 8;" :: "r"(saddr), "l"(g));
}
__device__ __forceinline__ void cp_commit() {
    asm volatile("cp.async.commit_group;");
}
__device__ __forceinline__ void cp_wait2() {
    asm volatile("cp.async.wait_group 2;");
}

// ---------------------------------------------------------------------------
// Kernel A: fused W+H box sums (x, y, x^2, y^2, xy), 2 outputs per thread.
// 11-slot cp.async staging pipeline (depth 3), float2 taps, incremental
// second output, register ring. Output stored as half2.
// grid = B*D*HSEGS, 80 threads, min-blocks 4 (regfile ceiling, R9 lesson).
// ---------------------------------------------------------------------------
#define KA_FETCH(ROW, SLOT) { \
    const int _r = (ROW); \
    if (_r >= 0 && _r < H) { \
        cp_async8(sx_base + (SLOT) * (SROW * 4) + (6 + w) * 4, x + pb + _r * W + w); \
        cp_async8(sy_base + (SLOT) * (SROW * 4) + (6 + w) * 4, y + pb + _r * W + w); \
    } else { \
        *(float2*)&sx[SLOT][6 + w] = make_float2(0.f, 0.f); \
        *(float2*)&sy[SLOT][6 + w] = make_float2(0.f, 0.f); \
    } \
    cp_commit(); }

#define KA_STEP(TT) { \
    cp_wait2(); \
    __syncthreads(); \
    { \
        const float2* rx2 = (const float2*)&sx[TT][w]; \
        const float2* ry2 = (const float2*)&sy[TT][w]; \
        float xv[14], yv[14]; \
        _Pragma("unroll") \
        for (int i = 0; i < 7; i++) { \
            float2 t2 = rx2[i]; xv[2*i] = t2.x; xv[2*i+1] = t2.y; \
            float2 u2 = ry2[i]; yv[2*i] = u2.x; yv[2*i+1] = u2.y; \
        } \
        float ax = xv[1], ay = yv[1]; \
        float axx = xv[1]*xv[1], ayy = yv[1]*yv[1], axy = xv[1]*yv[1]; \
        _Pragma("unroll") \
        for (int i = 2; i <= 11; i++) { \
            ax += xv[i]; ay += yv[i]; \
            axx = fmaf(xv[i], xv[i], axx); \
            ayy = fmaf(yv[i], yv[i], ayy); \
            axy = fmaf(xv[i], yv[i], axy); \
        } \
        float dax = xv[12] - xv[1], day = yv[12] - yv[1]; \
        float ax1 = ax + dax, ay1 = ay + day; \
        float axx1 = fmaf(dax, xv[12] + xv[1], axx); \
        float ayy1 = fmaf(day, yv[12] + yv[1], ayy); \
        float axy1 = fmaf(-xv[1], yv[1], fmaf(xv[12], yv[12], axy)); \
        rg0[TT] = make_float2(ax, ax1);   s0.x += ax;  s0.y += ax1; \
        rg1[TT] = make_float2(ay, ay1);   s1.x += ay;  s1.y += ay1; \
        rg2[TT] = make_float2(axx, axx1); s2.x += axx; s2.y += axx1; \
        rg3[TT] = make_float2(ayy, ayy1); s3.x += ayy; s3.y += ayy1; \
        rg4[TT] = make_float2(axy, axy1); s4.x += axy; s4.y += axy1; \
        if (r >= h0 && r < h1) { \
            float e0 = fabsf(xv[6] - yv[6]); \
            l1acc += (e0 < 1.f) ? 0.5f * e0 * e0 : e0 - 0.5f; \
            float e1 = fabsf(xv[7] - yv[7]); \
            l1acc += (e1 < 1.f) ? 0.5f * e1 * e1 : e1 - 0.5f; \
        } \
    } \
    KA_FETCH(r + 3, (TT + 3) % 11) \
    if (t >= 10) { \
        const int hh = h0 + t - 10; \
        const int o2 = (pb + hh * W + w) >> 1; \
        g_bufB[0 * (NVOX/2) + o2] = __float22half2_rn(s0); \
        g_bufB[1 * (NVOX/2) + o2] = __float22half2_rn(s1); \
        g_bufB[2 * (NVOX/2) + o2] = __float22half2_rn(s2); \
        g_bufB[3 * (NVOX/2) + o2] = __float22half2_rn(s3); \
        g_bufB[4 * (NVOX/2) + o2] = __float22half2_rn(s4); \
        float2 z; \
        z = rg0[(TT + 1) % 11]; s0.x -= z.x; s0.y -= z.y; \
        z = rg1[(TT + 1) % 11]; s1.x -= z.x; s1.y -= z.y; \
        z = rg2[(TT + 1) % 11]; s2.x -= z.x; s2.y -= z.y; \
        z = rg3[(TT + 1) % 11]; s3.x -= z.x; s3.y -= z.y; \
        z = rg4[(TT + 1) % 11]; s4.x -= z.x; s4.y -= z.y; \
    } \
    r++; t++; }

__global__ __launch_bounds__(KA_THREADS, 4) void kA_wh(const float* __restrict__ x,
                                                       const float* __restrict__ y) {
    __shared__ __align__(16) float sx[11][SROW];
    __shared__ __align__(16) float sy[11][SROW];
    __shared__ float red[KA_THREADS];

    const int bx = blockIdx.x;
    const int seg = bx % HSEGS;
    const int d = (bx / HSEGS) % D;
    const int b = bx / (HSEGS * D);
    const int w2 = threadIdx.x;        // 0..79
    const int w = 2 * w2;

    const int h0 = seg * HSEG_LEN;
    const int h1 = h0 + HSEG_LEN;
    const int pb = (b * D + d) * HW;

    const uint32_t sx_base = (uint32_t)__cvta_generic_to_shared(&sx[0][0]);
    const uint32_t sy_base = (uint32_t)__cvta_generic_to_shared(&sy[0][0]);

    // zero pads once (cp.async never touches indices 0..5 / 166..171)
    if (w2 < 12) {
        int p = (w2 < 6) ? w2 : (160 + w2);
#pragma unroll
        for (int s = 0; s < 11; s++) { sx[s][p] = 0.f; sy[s][p] = 0.f; }
    }

    // prologue: fetch rows h0-5 .. h0-3 into slots 0..2
    KA_FETCH(h0 - 5, 0)
    KA_FETCH(h0 - 4, 1)
    KA_FETCH(h0 - 3, 2)

    float2 s0 = {0.f, 0.f}, s1 = {0.f, 0.f}, s2 = {0.f, 0.f};
    float2 s3 = {0.f, 0.f}, s4 = {0.f, 0.f};
    float l1acc = 0.f;
    float2 rg0[11], rg1[11], rg2[11], rg3[11], rg4[11];
    int r = h0 - 5;
    int t = 0;

#pragma unroll 1
    for (int tc = 0; tc < 4; tc++) {
        KA_STEP(0) KA_STEP(1) KA_STEP(2) KA_STEP(3) KA_STEP(4) KA_STEP(5)
        KA_STEP(6) KA_STEP(7) KA_STEP(8) KA_STEP(9) KA_STEP(10)
    }
    KA_STEP(0) KA_STEP(1) KA_STEP(2) KA_STEP(3) KA_STEP(4) KA_STEP(5)

    // deterministic block reduction of l1acc over 80 threads
    red[w2] = l1acc;
    __syncthreads();
    if (w2 < 40) red[w2] += red[w2 + 40];
    __syncthreads();
    if (w2 < 20) red[w2] += red[w2 + 20];
    __syncthreads();
    if (w2 < 10) red[w2] += red[w2 + 10];
    __syncthreads();
    if (w2 < 5) red[w2] += red[w2 + 5];
    __syncthreads();
    if (w2 == 0) {
        g_l1part[bx] = red[0] + red[1] + red[2] + red[3] + red[4];
    }
}
#undef KA_STEP
#undef KA_FETCH

// ---------------------------------------------------------------------------
// SSIM numerator/denominator (no division)
// ---------------------------------------------------------------------------
__device__ __forceinline__ void ssim_nd(float s0, float s1, float s2,
                                        float s3, float s4,
                                        float& num, float& den) {
    float mux = s0 * INV_WIN3;
    float muy = s1 * INV_WIN3;
    float mux2 = mux * mux;
    float muy2 = muy * muy;
    float muxy = mux * muy;
    float sxx = s2 * INV_WIN3 - mux2;
    float syy = s3 * INV_WIN3 - muy2;
    float sxy = s4 * INV_WIN3 - muxy;
    num = (2.f * muxy + C1F) * (2.f * sxy + C2F);
    den = (mux2 + muy2 + C1F) * (sxx + syy + C2F) + 1e-8f;
}

__device__ __forceinline__ float clip_loss(float ssim) {
    float loss = (1.f - ssim) * 0.5f;
    return fminf(fmaxf(loss, 0.f), 1.f);
}

// half4 load (uint2) -> float4
__device__ __forceinline__ float4 ldh4(const __half2* p) {
    uint2 u = *reinterpret_cast<const uint2*>(p);
    __half2 h0 = *reinterpret_cast<__half2*>(&u.x);
    __half2 h1 = *reinterpret_cast<__half2*>(&u.y);
    float2 f0 = __half22float2(h0);
    float2 f1 = __half22float2(h1);
    return make_float4(f0.x, f0.y, f1.x, f1.y);
}

#define ACC4(S, V) { S.x += V.x; S.y += V.y; S.z += V.z; S.w += V.w; }
#define UPD4(S, A, Bv) { S.x += A.x - Bv.x; S.y += A.y - Bv.y; \
                         S.z += A.z - Bv.z; S.w += A.w - Bv.w; }

// ---------------------------------------------------------------------------
// Kernel B: box-sum along D + SSIM (Montgomery batched reciprocal: 1 division
// per 4 voxels) + block reduction. half4 loads, 4 w-outputs per thread,
// 2 h-rows/block, 16-deep d segments. grid = 1600, 80 threads.
// ---------------------------------------------------------------------------
__global__ __launch_bounds__(KB_THREADS) void kB_dpass_ssim() {
    __shared__ float red[KB_THREADS];

    const int bid = blockIdx.x;
    const int seg = bid % KB_SEGS;
    const int hq = (bid / KB_SEGS) % (H / KB_HBLK);
    const int b = bid / (KB_SEGS * (H / KB_HBLK));

    const int tid = threadIdx.x;
    const int lane = tid % (W / 4);    // 0..39, 4-wide w chunk
    const int row = tid / (W / 4);     // 0..1
    const int h = hq * KB_HBLK + row;

    const int d0 = seg * KB_SEGLEN;
    const int colh2 = (b * (D * HW) + h * W) / 2 + lane * 2;  // half2 units
    const int sth2 = HW / 2;

    const __half2* __restrict__ q0 = g_bufB + 0 * (NVOX / 2);
    const __half2* __restrict__ q1 = g_bufB + 1 * (NVOX / 2);
    const __half2* __restrict__ q2 = g_bufB + 2 * (NVOX / 2);
    const __half2* __restrict__ q3 = g_bufB + 3 * (NVOX / 2);
    const __half2* __restrict__ q4 = g_bufB + 4 * (NVOX / 2);

    float4 s0 = {0,0,0,0}, s1 = {0,0,0,0}, s2 = {0,0,0,0};
    float4 s3 = {0,0,0,0}, s4 = {0,0,0,0};
    {
        int lo = d0 - 5; if (lo < 0) lo = 0;
        int hi = d0 + 5; if (hi > D - 1) hi = D - 1;
        for (int d = lo; d <= hi; d++) {
            int id = colh2 + d * sth2;
            float4 v;
            v = ldh4(q0 + id); ACC4(s0, v)
            v = ldh4(q1 + id); ACC4(s1, v)
            v = ldh4(q2 + id); ACC4(s2, v)
            v = ldh4(q3 + id); ACC4(s3, v)
            v = ldh4(q4 + id); ACC4(s4, v)
        }
    }

    float acc = 0.f;
#pragma unroll 4
    for (int i = 0; i < KB_SEGLEN; i++) {
        const int d = d0 + i;
        const int dn = d + 6;
        const int dp = d - 5;

        float4 a0 = {0,0,0,0}, a1 = {0,0,0,0}, a2 = {0,0,0,0};
        float4 a3 = {0,0,0,0}, a4 = {0,0,0,0};
        float4 b0 = {0,0,0,0}, b1 = {0,0,0,0}, b2 = {0,0,0,0};
        float4 b3 = {0,0,0,0}, b4 = {0,0,0,0};
        if (dn < D) {
            int id = colh2 + dn * sth2;
            a0 = ldh4(q0 + id); a1 = ldh4(q1 + id); a2 = ldh4(q2 + id);
            a3 = ldh4(q3 + id); a4 = ldh4(q4 + id);
        }
        if (dp >= 0) {
            int id = colh2 + dp * sth2;
            b0 = ldh4(q0 + id); b1 = ldh4(q1 + id); b2 = ldh4(q2 + id);
            b3 = ldh4(q3 + id); b4 = ldh4(q4 + id);
        }

        // 4 SSIM ratios with a single reciprocal (Montgomery batch inversion)
        {
            float nA, dA, nB, dB, nC, dC, nD, dD;
            ssim_nd(s0.x, s1.x, s2.x, s3.x, s4.x, nA, dA);
            ssim_nd(s0.y, s1.y, s2.y, s3.y, s4.y, nB, dB);
            ssim_nd(s0.z, s1.z, s2.z, s3.z, s4.z, nC, dC);
            ssim_nd(s0.w, s1.w, s2.w, s3.w, s4.w, nD, dD);
            float dAB = dA * dB;
            float dCD = dC * dD;
            float r = __fdividef(1.0f, dAB * dCD);
            float ssimA = nA * (dB * dCD) * r;
            float ssimB = nB * (dA * dCD) * r;
            float ssimC = nC * (dAB * dD) * r;
            float ssimD = nD * (dAB * dC) * r;
            acc += clip_loss(ssimA);
            acc += clip_loss(ssimB);
            acc += clip_loss(ssimC);
            acc += clip_loss(ssimD);
        }

        UPD4(s0, a0, b0)
        UPD4(s1, a1, b1)
        UPD4(s2, a2, b2)
        UPD4(s3, a3, b3)
        UPD4(s4, a4, b4)
    }

    // deterministic block reduction over 80 threads
    red[tid] = acc;
    __syncthreads();
    if (tid < 40) red[tid] += red[tid + 40];
    __syncthreads();
    if (tid < 20) red[tid] += red[tid + 20];
    __syncthreads();
    if (tid < 10) red[tid] += red[tid + 10];
    __syncthreads();
    if (tid < 5) red[tid] += red[tid + 5];
    __syncthreads();
    if (tid == 0) {
        g_ssimpart[bid] = red[0] + red[1] + red[2] + red[3] + red[4];
    }
}

// ---------------------------------------------------------------------------
// Kernel C: final deterministic reduction.
// ---------------------------------------------------------------------------
__global__ __launch_bounds__(256) void kC_final(float* __restrict__ out) {
    __shared__ double sh[256];
    const int t = threadIdx.x;

    double a = 0.0;
    for (int i = t; i < A_BLOCKS; i += 256) a += (double)g_l1part[i];
    double bsum = 0.0;
    for (int i = t; i < KB_BLOCKS; i += 256) bsum += (double)g_ssimpart[i];

    sh[t] = a;
    __syncthreads();
#pragma unroll
    for (int s = 128; s > 0; s >>= 1) {
        if (t < s) sh[t] += sh[t + s];
        __syncthreads();
    }
    double l1sum = sh[0];
    __syncthreads();

    sh[t] = bsum;
    __syncthreads();
#pragma unroll
    for (int s = 128; s > 0; s >>= 1) {
        if (t < s) sh[t] += sh[t + s];
        __syncthreads();
    }

    if (t == 0) {
        double ssimsum = sh[0];
        double n = (double)NVOX;
        out[0] = (float)(0.85 * (ssimsum / n) + 0.15 * (l1sum / n));
    }
}

// ---------------------------------------------------------------------------
extern "C" void kernel_launch(void* const* d_in, const int* in_sizes, int n_in,
                              void* d_out, int out_size) {
    const float* pred = (const float*)d_in[0];
    const float* target = (const float*)d_in[1];
    float* out = (float*)d_out;

    kA_wh<<<A_BLOCKS, KA_THREADS>>>(pred, target);
    kB_dpass_ssim<<<KB_BLOCKS, KB_THREADS>>>();
    kC_final<<<1, 256>>>(out);
}